// round 17
// baseline (speedup 1.0000x reference)
#include <cuda_runtime.h>
#include <math.h>
#include <stdint.h>

#define BATCH 65536
#define IN_DIM 64
#define HID 128
#define CHOL 136
#define FULLM 0xffffffffu

// Scratch
__device__ float g_h1[BATCH * HID];
__device__ float g_h2[BATCH * HID];
__device__ float g_ld[BATCH * CHOL];
// Fragment-ordered tf32 weights: per (kb, nt, lane) -> (b0, b1)
__device__ float2 g_F1[(IN_DIM / 8) * 16 * 32];
__device__ float2 g_F2[(HID / 8)    * 16 * 32];
__device__ float2 g_F3[(HID / 8)    * 17 * 32];

__device__ __forceinline__ uint32_t to_tf32(float v)
{
    uint32_t r;
    asm("cvt.rna.tf32.f32 %0, %1;" : "=r"(r) : "f"(v));
    return r;
}

__global__ void build_wfrag(const float* __restrict__ W, float2* __restrict__ F,
                            int K, int N, int NT)
{
    int idx = blockIdx.x * 256 + threadIdx.x;
    int total = (K / 8) * NT * 32;
    if (idx >= total) return;
    int lane = idx & 31;
    int nt = (idx >> 5) % NT;
    int kb = (idx >> 5) / NT;
    int grp = lane >> 2, tig = lane & 3;
    int col = nt * 8 + grp;
    float w0 = 0.f, w1 = 0.f;
    if (col < N) {
        w0 = W[(size_t)(kb * 8 + tig) * N + col];
        w1 = W[(size_t)(kb * 8 + tig + 4) * N + col];
    }
    F[idx] = make_float2(__uint_as_float(to_tf32(w0)),
                         __uint_as_float(to_tf32(w1)));
}

// ---------------------------------------------------------------------------
// cp.async helpers
// ---------------------------------------------------------------------------
__device__ __forceinline__ void cp16(uint32_t dst, const void* src) {
    asm volatile("cp.async.ca.shared.global [%0], [%1], 16;\n" :: "r"(dst), "l"(src));
}
#define CP_COMMIT asm volatile("cp.async.commit_group;\n" ::: "memory")
#define CP_WAIT1  asm volatile("cp.async.wait_group 1;\n" ::: "memory")

__device__ __forceinline__ void mma_tf32(float* c, uint32_t a0, uint32_t a1,
                                         uint32_t a2, uint32_t a3,
                                         uint32_t b0, uint32_t b1)
{
    asm volatile(
        "mma.sync.aligned.m16n8k8.row.col.f32.tf32.tf32.f32 "
        "{%0,%1,%2,%3}, {%4,%5,%6,%7}, {%8,%9}, {%0,%1,%2,%3};\n"
        : "+f"(c[0]), "+f"(c[1]), "+f"(c[2]), "+f"(c[3])
        : "r"(a0), "r"(a1), "r"(a2), "r"(a3), "r"(b0), "r"(b1));
}

// ---------------------------------------------------------------------------
// Tensor-core SGEMM (R16, unchanged): raw tf32 mma, fragment-ordered W,
// cp.async double-buffered staging. 256 thr, tile 128x64, K-chunk 16.
// ---------------------------------------------------------------------------
template<int ACT>
__global__ __launch_bounds__(256) void gemm_tf32(
    const float* __restrict__ A, const float2* __restrict__ Fg,
    const float* __restrict__ bias, float* __restrict__ C,
    int M, int N, int K, int NT)
{
    __shared__ float  sA[2][128][20];
    __shared__ float2 sF[2][2][8][32];

    const int tid  = threadIdx.x;
    const int warp = tid >> 5, lane = tid & 31;
    const int grp  = lane >> 2, tig = lane & 3;
    const int bm   = blockIdx.x * 128, bn = blockIdx.y * 64;
    const int bn8  = bn >> 3;
    const int wrow = warp * 16;
    const int ntblk = min(8, NT - bn8);

    const int a_row0 = tid >> 2, a_k4 = (tid & 3) * 4;

    float c[8][4];
    #pragma unroll
    for (int t = 0; t < 8; t++)
        #pragma unroll
        for (int j = 0; j < 4; j++) c[t][j] = 0.f;

    const int nk = K >> 4;

    #define PREFETCH(KT, P)                                                    \
    do {                                                                       \
        int k0_ = (KT) << 4;                                                   \
        _Pragma("unroll")                                                      \
        for (int i = 0; i < 2; i++) {                                          \
            int row = a_row0 + i * 64;                                         \
            uint32_t d = (uint32_t)__cvta_generic_to_shared(&sA[P][row][a_k4]);\
            cp16(d, &A[(size_t)(bm + row) * K + k0_ + a_k4]);                  \
        }                                                                      \
        {                                                                      \
            int kb8 = tid >> 7, t = tid & 127;                                 \
            if (t < ntblk * 16) {                                              \
                uint32_t d = (uint32_t)__cvta_generic_to_shared(               \
                    (float4*)&sF[P][kb8][0][0] + t);                           \
                cp16(d, (const float4*)(Fg +                                   \
                    ((size_t)((k0_ >> 3) + kb8) * NT + bn8) * 32) + t);        \
            }                                                                  \
        }                                                                      \
    } while (0)

    PREFETCH(0, 0);
    CP_COMMIT;

    for (int kt = 0; kt < nk; kt++) {
        const int p = kt & 1;
        if (kt + 1 < nk) PREFETCH(kt + 1, (kt + 1) & 1);
        CP_COMMIT;
        CP_WAIT1;
        __syncthreads();

        #pragma unroll
        for (int k8 = 0; k8 < 2; k8++) {
            uint32_t a0 = to_tf32(sA[p][wrow + grp    ][k8 * 8 + tig    ]);
            uint32_t a1 = to_tf32(sA[p][wrow + grp + 8][k8 * 8 + tig    ]);
            uint32_t a2 = to_tf32(sA[p][wrow + grp    ][k8 * 8 + tig + 4]);
            uint32_t a3 = to_tf32(sA[p][wrow + grp + 8][k8 * 8 + tig + 4]);

            if (ntblk == 8) {
                #pragma unroll
                for (int nt = 0; nt < 8; nt++) {
                    float2 bf = sF[p][k8][nt][lane];
                    mma_tf32(c[nt], a0, a1, a2, a3,
                             __float_as_uint(bf.x), __float_as_uint(bf.y));
                }
            } else {
                for (int nt = 0; nt < ntblk; nt++) {
                    float2 bf = sF[p][k8][nt][lane];
                    mma_tf32(c[nt], a0, a1, a2, a3,
                             __float_as_uint(bf.x), __float_as_uint(bf.y));
                }
            }
        }
        __syncthreads();
    }
    #undef PREFETCH

    const int r0 = bm + wrow + grp;
    for (int nt = 0; nt < ntblk; nt++) {
        int col = bn + nt * 8 + 2 * tig;
        if (col >= N) continue;
        bool c2ok = (col + 1 < N);
        float b0v = bias[col];
        float b1v = c2ok ? bias[col + 1] : 0.f;
        #pragma unroll
        for (int h = 0; h < 2; h++) {
            float v0 = c[nt][2 * h + 0] + b0v;
            float v1 = c[nt][2 * h + 1] + b1v;
            if (ACT == 0) {
                v0 = (v0 > 0.f) ? v0 : 0.01f * v0;
                v1 = (v1 > 0.f) ? v1 : 0.01f * v1;
            } else {
                v0 = tanhf(v0); v1 = tanhf(v1);
            }
            float* cp = &C[(size_t)(r0 + 8 * h) * N + col];
            if (c2ok) { cp[0] = v0; cp[1] = v1; }
            else      { cp[0] = v0; }
        }
    }
}

// ---------------------------------------------------------------------------
// PSD head with tensor-core 16x16x16 multiplies (one warp per matrix):
//   Q2 = Q·Q;  Y = I + (2/3)Q + (1/3)Q2;  M = Q + Q2·Y
//   M2 = M·M;  Z = I/2 + M/6 + M2/24;     Ct = I + M + M2·Z
//   out = Ct / sqrt(tr(Ct^2))
// Buffers per warp: X (Q then M), T (squares), U (Y/Z and products), each
// 16 rows x stride 18 (even stride -> aligned float2 fragment stores).
// Products are tf32 (error ~1e-5 absolute, attenuated); all elementwise
// fusions fp32 on lane-private positions.  Only __syncwarp, no block syncs.
// ---------------------------------------------------------------------------
#define PRST 18
#define PBUF 288      // 16 * 18

// D = S · Y  (16x16x16, row-major stride PRST).  D may alias Y.
__device__ __forceinline__ void wmm16(const float* __restrict__ S,
                                      const float* __restrict__ Y,
                                      float* __restrict__ D,
                                      int grp, int tig)
{
    uint32_t a[2][4];
    #pragma unroll
    for (int k8 = 0; k8 < 2; k8++) {
        a[k8][0] = to_tf32(S[(grp    ) * PRST + k8 * 8 + tig    ]);
        a[k8][1] = to_tf32(S[(grp + 8) * PRST + k8 * 8 + tig    ]);
        a[k8][2] = to_tf32(S[(grp    ) * PRST + k8 * 8 + tig + 4]);
        a[k8][3] = to_tf32(S[(grp + 8) * PRST + k8 * 8 + tig + 4]);
    }
    float c0[4] = {0.f, 0.f, 0.f, 0.f};
    float c1[4] = {0.f, 0.f, 0.f, 0.f};
    #pragma unroll
    for (int k8 = 0; k8 < 2; k8++) {
        uint32_t b00 = to_tf32(Y[(k8 * 8 + tig    ) * PRST + grp    ]);
        uint32_t b01 = to_tf32(Y[(k8 * 8 + tig + 4) * PRST + grp    ]);
        uint32_t b10 = to_tf32(Y[(k8 * 8 + tig    ) * PRST + 8 + grp]);
        uint32_t b11 = to_tf32(Y[(k8 * 8 + tig + 4) * PRST + 8 + grp]);
        mma_tf32(c0, a[k8][0], a[k8][1], a[k8][2], a[k8][3], b00, b01);
        mma_tf32(c1, a[k8][0], a[k8][1], a[k8][2], a[k8][3], b10, b11);
    }
    __syncwarp();   // all reads of (possibly aliased) Y complete
    *(float2*)&D[(grp    ) * PRST + 2 * tig    ] = make_float2(c0[0], c0[1]);
    *(float2*)&D[(grp + 8) * PRST + 2 * tig    ] = make_float2(c0[2], c0[3]);
    *(float2*)&D[(grp    ) * PRST + 8 + 2 * tig] = make_float2(c1[0], c1[1]);
    *(float2*)&D[(grp + 8) * PRST + 8 + 2 * tig] = make_float2(c1[2], c1[3]);
    __syncwarp();
}

__global__ __launch_bounds__(256) void psd_expm(
    const float* __restrict__ ldata, float* __restrict__ out)
{
    __shared__ __align__(16) float sh[8 * 3 * PBUF];   // 27648 B
    const int tid  = threadIdx.x;
    const int warp = tid >> 5, l = tid & 31;
    const int grp  = l >> 2, tig = l & 3;
    const int b    = blockIdx.x * 8 + warp;
    float* X = sh + warp * 3 * PBUF;
    float* T = X + PBUF;
    float* U = T + PBUF;

    // Stage 136 tanh values into U.
    const float* rowp = ldata + (size_t)b * CHOL;
    for (int j = l; j < CHOL; j += 32) U[j] = rowp[j];
    __syncwarp();

    // Build Q = L + L^T into X (fp32).  Lane handles idx = k*32 + l.
    #pragma unroll
    for (int k = 0; k < 8; k++) {
        int idx = k * 32 + l;
        int r = idx >> 4, c = idx & 15;
        int hi = (r > c) ? r : c;
        int lo = r + c - hi;
        float v = U[hi * (hi + 1) / 2 + lo];
        X[r * PRST + c] = (r == c) ? 2.f * v : v;
    }
    __syncwarp();

    // T = Q·Q
    wmm16(X, X, T, grp, tig);

    // U = I + (2/3)Q + (1/3)Q2
    #pragma unroll
    for (int k = 0; k < 8; k++) {
        int idx = k * 32 + l;
        int r = idx >> 4, c = idx & 15;
        int o = r * PRST + c;
        U[o] = ((r == c) ? 1.f : 0.f) + (2.f / 3.f) * X[o] + (1.f / 3.f) * T[o];
    }
    __syncwarp();

    // U = Q2·U  (product), then X = Q + U  (X becomes M)
    wmm16(T, U, U, grp, tig);
    #pragma unroll
    for (int k = 0; k < 8; k++) {
        int idx = k * 32 + l;
        int o = (idx >> 4) * PRST + (idx & 15);
        X[o] = X[o] + U[o];
    }
    __syncwarp();

    // T = M·M
    wmm16(X, X, T, grp, tig);

    // U = I/2 + M/6 + M2/24
    #pragma unroll
    for (int k = 0; k < 8; k++) {
        int idx = k * 32 + l;
        int r = idx >> 4, c = idx & 15;
        int o = r * PRST + c;
        U[o] = ((r == c) ? 0.5f : 0.f) + (1.f / 6.f) * X[o] + (1.f / 24.f) * T[o];
    }
    __syncwarp();

    // U = M2·U ; then Ct = I + M + U, trace inline.
    wmm16(T, U, U, grp, tig);

    float ct[8];
    float tr = 0.f;
    #pragma unroll
    for (int k = 0; k < 8; k++) {
        int idx = k * 32 + l;
        int r = idx >> 4, c = idx & 15;
        int o = r * PRST + c;
        float v = ((r == c) ? 1.f : 0.f) + X[o] + U[o];
        ct[k] = v;
        tr = fmaf(v, v, tr);
    }
    #pragma unroll
    for (int o = 16; o; o >>= 1) tr += __shfl_xor_sync(FULLM, tr, o);
    float scale = rsqrtf(tr);

    float* op = out + (size_t)b * 256;
    #pragma unroll
    for (int k = 0; k < 8; k++)
        op[k * 32 + l] = ct[k] * scale;
}

// ---------------------------------------------------------------------------
extern "C" void kernel_launch(void* const* d_in, const int* in_sizes, int n_in,
                              void* d_out, int out_size)
{
    const float* x  = (const float*)d_in[0];
    const float* W1 = (const float*)d_in[1];
    const float* b1 = (const float*)d_in[2];
    const float* W2 = (const float*)d_in[3];
    const float* b2 = (const float*)d_in[4];
    const float* W3 = (const float*)d_in[5];
    const float* b3 = (const float*)d_in[6];
    float* out = (float*)d_out;

    float *h1, *h2, *ldp;
    float2 *f1, *f2, *f3;
    cudaGetSymbolAddress((void**)&h1,  g_h1);
    cudaGetSymbolAddress((void**)&h2,  g_h2);
    cudaGetSymbolAddress((void**)&ldp, g_ld);
    cudaGetSymbolAddress((void**)&f1,  g_F1);
    cudaGetSymbolAddress((void**)&f2,  g_F2);
    cudaGetSymbolAddress((void**)&f3,  g_F3);

    build_wfrag<<<((IN_DIM/8)*16*32 + 255) / 256, 256>>>(W1, f1, IN_DIM, HID, 16);
    build_wfrag<<<((HID/8)*16*32   + 255) / 256, 256>>>(W2, f2, HID,    HID, 16);
    build_wfrag<<<((HID/8)*17*32   + 255) / 256, 256>>>(W3, f3, HID,   CHOL, 17);

    dim3 blk(256);
    gemm_tf32<0><<<dim3(BATCH / 128, 2), blk>>>(x,  f1, b1, h1,  BATCH, HID,  IN_DIM, 16);
    gemm_tf32<0><<<dim3(BATCH / 128, 2), blk>>>(h1, f2, b2, h2,  BATCH, HID,  HID,    16);
    gemm_tf32<1><<<dim3(BATCH / 128, 3), blk>>>(h2, f3, b3, ldp, BATCH, CHOL, HID,    17);
    psd_expm<<<BATCH / 8, 256>>>(ldp, out);
}